// round 9
// baseline (speedup 1.0000x reference)
#include <cuda_runtime.h>

// SSIM loss, fully fused one-kernel version, 4-plane formulation.
// img1, img2: [32,3,512,512] fp32. Output: scalar fp32 = 1 - mean(ssim_map).
//
// Planes: conv(x), conv(y), conv(x^2+y^2), conv(x*y) (x²,y² folded pre-conv).
// Per block: one (plane, 88-row band), 512 threads. Vertical 11-tap conv via
// 11-phase register accumulator ring (1 col/thread), 4-row groups into
// double-buffered smem; horizontal 11-tap conv + SSIM at 4 px/thread (LDS.128).
// R7 structure exactly; band doubled to 88 rows to amortize the 10-row warmup.

#define HW       512
#define NPLANES  96
#define BAND     88
#define NBANDS   6
#define NBLK     (NBANDS * NPLANES)   // 576
#define VB       528
#define VB4      (VB / 4)
#define SMEM_DYN (2 * 4 * 4 * VB4 * 16)   // 67584 bytes

namespace {
constexpr double G_[6] = {0.0038659201595884, 0.0285655007845504,
                          0.1353352832366127, 0.4111122905071874,
                          0.8007374029168081, 1.0};
constexpr double GSUM = 2.0*(G_[0]+G_[1]+G_[2]+G_[3]+G_[4]) + 1.0;
constexpr float gwf(int j){ return (float)(G_[j < 6 ? j : 10 - j] / GSUM); }
}

__device__ constexpr float GW[11] = {
    gwf(0), gwf(1), gwf(2), gwf(3), gwf(4), gwf(5),
    gwf(6), gwf(7), gwf(8), gwf(9), gwf(10)};

__device__ float    g_part[NBLK];
__device__ unsigned g_count = 0;

// Deposit j of ingested row (ring phase PH) -> slot (PH+j+6)%11, belonging to
// output row o = r + j - 5. JMIN masks prologue deposits (only o >= o0).
// j == 10 is always the FIRST write to its slot since that slot's emit
// (validated R6/R7: identical rel_err) -> plain MUL, no ring init anywhere.
// Planes: 0 = x, 1 = y, 2 = x^2 + y^2, 3 = x*y.
template<int PH, int JMIN>
__device__ __forceinline__ void ingest(float (&A)[4][11], float v1, float v2)
{
    const float q2  = v1 * v1;
    const float q23 = fmaf(v2, v2, q2);
    const float q4  = v1 * v2;
#pragma unroll
    for (int j = JMIN; j < 11; ++j) {
        const int   s = (PH + j + 6) % 11;
        const float w = GW[j];
        if (j == 10) {
            A[0][s] = w * v1;
            A[1][s] = w * v2;
            A[2][s] = w * q23;
            A[3][s] = w * q4;
        } else {
            A[0][s] = fmaf(w, v1,  A[0][s]);
            A[1][s] = fmaf(w, v2,  A[1][s]);
            A[2][s] = fmaf(w, q23, A[2][s]);
            A[3][s] = fmaf(w, q4,  A[3][s]);
        }
    }
}

__global__ __launch_bounds__(512, 1)
void ssim_main(const float* __restrict__ img1, const float* __restrict__ img2,
               float* __restrict__ out)
{
    extern __shared__ float4 dynbuf[];   // [2][4][4][VB4]
#define VBUF(B, P, S) ((float*)(dynbuf + (((B)*4 + (P))*4 + (S)) * VB4))

    const int c     = threadIdx.x;
    const int band  = blockIdx.x;
    const int plane = blockIdx.y;
    const int o0    = band * BAND;
    const float* __restrict__ p1 = img1 + (size_t)plane * HW * HW;
    const float* __restrict__ p2 = img2 + (size_t)plane * HW * HW;

    __shared__ float  red[16];
    __shared__ double sd[512];
    __shared__ int    amLast;

    // one-time zero of column borders (emits only touch [5,516])
#pragma unroll
    for (int b = 0; b < 2; ++b)
#pragma unroll
        for (int p = 0; p < 4; ++p)
#pragma unroll
            for (int s = 0; s < 4; ++s) {
                float* bb = VBUF(b, p, s);
                if (c < 5)    bb[c] = 0.f;
                if (c >= 501) bb[c + 16] = 0.f;   // 517..527
            }

    float acc[4][11];   // no init: first touch of every slot is the j==10 MUL

    __syncthreads();

    // prefetch banks: bank (G+1)&1 holds ingest rows for group G+1
    // (LOADS(G) fetches rows o0+4(G+1)+5+i, i.e. group G+1's ingest rows)
    float nv1[2][4], nv2[2][4];
#define LOADS(G) {                                                           \
        _Pragma("unroll")                                                    \
        for (int i = 0; i < 4; ++i) {                                        \
            const int  r_  = o0 + 4 * (G) + 9 + i;                           \
            const bool ok_ = r_ < HW;                                        \
            nv1[((G) + 1) & 1][i] = ok_ ? __ldg(&p1[(size_t)r_ * HW + c]) : 0.f; \
            nv2[((G) + 1) & 1][i] = ok_ ? __ldg(&p2[(size_t)r_ * HW + c]) : 0.f; \
        } }

    // issue group-0 ingest loads first; prologue FMA chain hides the latency
    LOADS(-1)

    // ── prologue: rows o0-5 .. o0+4, JMIN = 10-i masking ──
#define PROLOG(i) {                                                          \
        const int  r_  = o0 - 5 + (i);                                       \
        const bool ok_ = (unsigned)r_ < (unsigned)HW;                        \
        const float v1_ = ok_ ? __ldg(&p1[(size_t)r_ * HW + c]) : 0.f;       \
        const float v2_ = ok_ ? __ldg(&p2[(size_t)r_ * HW + c]) : 0.f;       \
        ingest<((i) + 6) % 11, 10 - (i)>(acc, v1_, v2_); }
    PROLOG(0) PROLOG(1) PROLOG(2) PROLOG(3) PROLOG(4)
    PROLOG(5) PROLOG(6) PROLOG(7) PROLOG(8) PROLOG(9)
#undef PROLOG

    // ingest + emit sub-row i of group G: row o0+4G+5+i, slot (4G+i)%11
#define ING(G, i) {                                                          \
        ingest<((4 * (G) + (i)) + 5) % 11, 0>(acc, nv1[(G) & 1][(i)],        \
                                              nv2[(G) & 1][(i)]);            \
        _Pragma("unroll")                                                    \
        for (int p = 0; p < 4; ++p)                                          \
            VBUF((G) & 1, p, (i))[c + 5] = acc[p][(4 * (G) + (i)) % 11]; }

    float lsum = 0.f;
    const int rr = c >> 7;            // horizontal: row within group
    const int cq = c & 127;           // horizontal: float4 index

    // horizontal conv + SSIM for group G out of buffer B (R7 shape)
#define HSTEP(G, B) {                                                        \
        float hr[4][4];                                                      \
        _Pragma("unroll")                                                    \
        for (int p = 0; p < 4; ++p) {                                        \
            const float4* q = dynbuf + (((B)*4 + p)*4 + rr) * VB4 + cq;      \
            const float4 A = q[0], Bv = q[1], Cv = q[2], D = q[3];           \
            const float v[16] = {A.x, A.y, A.z, A.w,  Bv.x, Bv.y, Bv.z, Bv.w,\
                                 Cv.x, Cv.y, Cv.z, Cv.w,  D.x, D.y, D.z, D.w};\
            _Pragma("unroll")                                                \
            for (int i = 0; i < 4; ++i) {                                    \
                float s = GW[0] * v[i];                                      \
                _Pragma("unroll")                                            \
                for (int k = 1; k < 11; ++k) s = fmaf(GW[k], v[i + k], s);   \
                hr[p][i] = s;                                                \
            }                                                                \
        }                                                                    \
        const int o = o0 + 4 * (G) + rr;                                     \
        if (o < HW) {                                                        \
            _Pragma("unroll")                                                \
            for (int i = 0; i < 4; ++i) {                                    \
                const float C1 = 1e-4f, C2 = 9e-4f;                          \
                const float m1 = hr[0][i], m2 = hr[1][i];                    \
                const float mu12 = m1 * m2;                                  \
                const float msum = fmaf(m1, m1, m2 * m2);                    \
                const float Anum = 2.f * mu12 + C1;                          \
                const float Bnum = 2.f * (hr[3][i] - mu12) + C2;             \
                const float Cden = msum + C1;                                \
                const float Dden = (hr[2][i] - msum) + C2;                   \
                lsum += __fdividef(Anum * Bnum, Cden * Dden);                \
            }                                                                \
        } }

    // group 0: prefetch group-1 rows, ingest bank 0, emit buf 0
    LOADS(0)
    ING(0, 0) ING(0, 1) ING(0, 2) ING(0, 3)

#define GBODY(G) {                                                           \
        __syncthreads();                                                     \
        if ((G) < 21) { LOADS(G) }                                           \
        HSTEP((G) - 1, ((G) - 1) & 1)                                        \
        ING(G, 0) ING(G, 1) ING(G, 2) ING(G, 3) }
    GBODY(1)  GBODY(2)  GBODY(3)  GBODY(4)  GBODY(5)
    GBODY(6)  GBODY(7)  GBODY(8)  GBODY(9)  GBODY(10)
    GBODY(11) GBODY(12) GBODY(13) GBODY(14) GBODY(15)
    GBODY(16) GBODY(17) GBODY(18) GBODY(19) GBODY(20)
    GBODY(21)
#undef GBODY

    __syncthreads();
    HSTEP(21, 1)

#undef HSTEP
#undef ING
#undef LOADS
#undef VBUF

    // ── block reduction ──
    float v = lsum;
#pragma unroll
    for (int off = 16; off; off >>= 1)
        v += __shfl_xor_sync(0xFFFFFFFFu, v, off);
    if ((c & 31) == 0) red[c >> 5] = v;
    __syncthreads();

    if (c == 0) {
        float bs = 0.f;
#pragma unroll
        for (int w = 0; w < 16; ++w) bs += red[w];
        g_part[plane * NBANDS + band] = bs;
        __threadfence();
        const unsigned t = atomicAdd(&g_count, 1u);
        amLast = (t == NBLK - 1);
    }
    __syncthreads();

    if (amLast) {
        __threadfence();
        double s = 0.0;
        for (int i = c; i < NBLK; i += 512) s += (double)g_part[i];
        sd[c] = s;
        __syncthreads();
#pragma unroll
        for (int k = 256; k > 0; k >>= 1) {
            if (c < k) sd[c] += sd[c + k];
            __syncthreads();
        }
        if (c == 0) {
            out[0]  = (float)(1.0 - sd[0] / 25165824.0);  // 32*3*512*512
            g_count = 0;                                   // reset for replay
        }
    }
}

extern "C" void kernel_launch(void* const* d_in, const int* in_sizes, int n_in,
                              void* d_out, int out_size)
{
    (void)in_sizes; (void)n_in; (void)out_size;
    const float* img1 = (const float*)d_in[0];
    const float* img2 = (const float*)d_in[1];
    cudaFuncSetAttribute(ssim_main, cudaFuncAttributeMaxDynamicSharedMemorySize,
                         SMEM_DYN);
    dim3 grid(NBANDS, NPLANES);
    ssim_main<<<grid, 512, SMEM_DYN>>>(img1, img2, (float*)d_out);
}

// round 10
// speedup vs baseline: 1.0390x; 1.0390x over previous
#include <cuda_runtime.h>

// SSIM loss, fully fused one-kernel version, 4-plane formulation.
// img1, img2: [32,3,512,512] fp32. Output: scalar fp32 = 1 - mean(ssim_map).
//
// Planes: conv(x), conv(y), conv(x^2+y^2), conv(x*y) (x²,y² folded pre-conv).
// Per block: one (plane, 44-row band), 512 threads. Vertical 11-tap conv via
// 11-phase register accumulator ring (1 col/thread), 4-row groups into
// double-buffered smem; horizontal 11-tap conv + SSIM at 4 px/thread (LDS.128).
// Bands 1..10 access only provably in-range rows/outputs -> guard-free
// template path; bands 0 and 11 take the guarded path.

#define HW       512
#define NPLANES  96
#define BAND     44
#define NBANDS   12
#define NBLK     (NBANDS * NPLANES)   // 1152
#define VB       528
#define VB4      (VB / 4)
#define SMEM_DYN (2 * 4 * 4 * VB4 * 16)   // 67584 bytes

namespace {
constexpr double G_[6] = {0.0038659201595884, 0.0285655007845504,
                          0.1353352832366127, 0.4111122905071874,
                          0.8007374029168081, 1.0};
constexpr double GSUM = 2.0*(G_[0]+G_[1]+G_[2]+G_[3]+G_[4]) + 1.0;
constexpr float gwf(int j){ return (float)(G_[j < 6 ? j : 10 - j] / GSUM); }
}

__device__ constexpr float GW[11] = {
    gwf(0), gwf(1), gwf(2), gwf(3), gwf(4), gwf(5),
    gwf(6), gwf(7), gwf(8), gwf(9), gwf(10)};

__device__ float    g_part[NBLK];
__device__ unsigned g_count = 0;

// Deposit j of ingested row (ring phase PH) -> slot (PH+j+6)%11, belonging to
// output row o = r + j - 5. JMIN masks prologue deposits (only o >= o0).
// j == 10 is always the FIRST write to its slot since that slot's emit
// (validated R6/R7: identical rel_err) -> plain MUL, no ring init anywhere.
// Planes: 0 = x, 1 = y, 2 = x^2 + y^2, 3 = x*y.
template<int PH, int JMIN>
__device__ __forceinline__ void ingest(float (&A)[4][11], float v1, float v2)
{
    const float q2  = v1 * v1;
    const float q23 = fmaf(v2, v2, q2);
    const float q4  = v1 * v2;
#pragma unroll
    for (int j = JMIN; j < 11; ++j) {
        const int   s = (PH + j + 6) % 11;
        const float w = GW[j];
        if (j == 10) {
            A[0][s] = w * v1;
            A[1][s] = w * v2;
            A[2][s] = w * q23;
            A[3][s] = w * q4;
        } else {
            A[0][s] = fmaf(w, v1,  A[0][s]);
            A[1][s] = fmaf(w, v2,  A[1][s]);
            A[2][s] = fmaf(w, q23, A[2][s]);
            A[3][s] = fmaf(w, q4,  A[3][s]);
        }
    }
}

// Whole 44-row band. GUARD=false: all row/output indices provably in range
// (bands 1..10: prologue rows >= 39, max ingest row o0+48 <= 488, outputs
// <= 483). GUARD=true: range checks on loads and the output accumulate.
template<bool GUARD>
__device__ __forceinline__ float band_body(
    const float* __restrict__ p1, const float* __restrict__ p2,
    int o0, float4* dynbuf, int c, int rr, int cq)
{
    float acc[4][11];   // no init: first touch of every slot is the j==10 MUL
    float nv1[2][4], nv2[2][4];
    float lsum = 0.f;

#define VBUF(B, P, S) ((float*)(dynbuf + (((B)*4 + (P))*4 + (S)) * VB4))
#define GLD(pp, r_) ((!GUARD || (unsigned)(r_) < (unsigned)HW) \
                       ? __ldg(&(pp)[(size_t)(r_) * HW + c]) : 0.f)

    // prefetch banks: bank (G+1)&1 holds ingest rows for group G+1
#define LOADS(G) {                                                          \
        _Pragma("unroll")                                                   \
        for (int i = 0; i < 4; ++i) {                                       \
            const int r_ = o0 + 4 * (G) + 9 + i;                            \
            nv1[((G) + 1) & 1][i] = GLD(p1, r_);                            \
            nv2[((G) + 1) & 1][i] = GLD(p2, r_);                            \
        } }

    // group-0 ingest loads first; the prologue FMA chain hides their latency
    LOADS(-1)

    // ── prologue: rows o0-5 .. o0+4, JMIN = 10-i masking ──
#define PROLOG(i) {                                                         \
        const int r_ = o0 - 5 + (i);                                        \
        const float v1_ = GLD(p1, r_);                                      \
        const float v2_ = GLD(p2, r_);                                      \
        ingest<((i) + 6) % 11, 10 - (i)>(acc, v1_, v2_); }
    PROLOG(0) PROLOG(1) PROLOG(2) PROLOG(3) PROLOG(4)
    PROLOG(5) PROLOG(6) PROLOG(7) PROLOG(8) PROLOG(9)
#undef PROLOG

    // ingest + emit sub-row i of group G: row o0+4G+5+i, slot (4G+i)%11
#define ING(G, i) {                                                         \
        ingest<((4 * (G) + (i)) + 5) % 11, 0>(acc, nv1[(G) & 1][(i)],       \
                                              nv2[(G) & 1][(i)]);           \
        _Pragma("unroll")                                                   \
        for (int p = 0; p < 4; ++p)                                         \
            VBUF((G) & 1, p, (i))[c + 5] = acc[p][(4 * (G) + (i)) % 11]; }

    // horizontal conv + SSIM for group G out of buffer B
#define HSTEP(G, B) {                                                       \
        float hr[4][4];                                                     \
        _Pragma("unroll")                                                   \
        for (int p = 0; p < 4; ++p) {                                       \
            const float4* q = dynbuf + (((B)*4 + p)*4 + rr) * VB4 + cq;     \
            const float4 A = q[0], Bv = q[1], Cv = q[2], D = q[3];          \
            const float v[16] = {A.x, A.y, A.z, A.w,  Bv.x, Bv.y, Bv.z, Bv.w, \
                                 Cv.x, Cv.y, Cv.z, Cv.w,  D.x, D.y, D.z, D.w}; \
            _Pragma("unroll")                                               \
            for (int i = 0; i < 4; ++i) {                                   \
                float s = GW[0] * v[i];                                     \
                _Pragma("unroll")                                           \
                for (int k = 1; k < 11; ++k) s = fmaf(GW[k], v[i + k], s);  \
                hr[p][i] = s;                                               \
            }                                                               \
        }                                                                   \
        if (!GUARD || (o0 + 4 * (G) + rr) < HW) {                           \
            _Pragma("unroll")                                               \
            for (int i = 0; i < 4; ++i) {                                   \
                const float C1 = 1e-4f, C2 = 9e-4f;                         \
                const float m1 = hr[0][i], m2 = hr[1][i];                   \
                const float mu12 = m1 * m2;                                 \
                const float msum = fmaf(m1, m1, m2 * m2);                   \
                const float Anum = 2.f * mu12 + C1;                         \
                const float Bnum = 2.f * (hr[3][i] - mu12) + C2;            \
                const float Cden = msum + C1;                               \
                const float Dden = (hr[2][i] - msum) + C2;                  \
                lsum += __fdividef(Anum * Bnum, Cden * Dden);               \
            }                                                               \
        } }

    // group 0: prefetch group-1 rows, ingest bank 0, emit buf 0
    LOADS(0)
    ING(0, 0) ING(0, 1) ING(0, 2) ING(0, 3)

#define GBODY(G) {                                                          \
        __syncthreads();                                                    \
        if ((G) < 10) { LOADS(G) }                                          \
        HSTEP((G) - 1, ((G) - 1) & 1)                                       \
        ING(G, 0) ING(G, 1) ING(G, 2) ING(G, 3) }
    GBODY(1) GBODY(2) GBODY(3) GBODY(4) GBODY(5)
    GBODY(6) GBODY(7) GBODY(8) GBODY(9) GBODY(10)
#undef GBODY

    __syncthreads();
    HSTEP(10, 0)

#undef HSTEP
#undef ING
#undef LOADS
#undef PROLOGX
#undef GLD
#undef VBUF
    return lsum;
}

__global__ __launch_bounds__(512, 1)
void ssim_main(const float* __restrict__ img1, const float* __restrict__ img2,
               float* __restrict__ out)
{
    extern __shared__ float4 dynbuf[];   // [2][4][4][VB4]

    const int c     = threadIdx.x;
    const int band  = blockIdx.x;
    const int plane = blockIdx.y;
    const int o0    = band * BAND;
    const float* __restrict__ p1 = img1 + (size_t)plane * HW * HW;
    const float* __restrict__ p2 = img2 + (size_t)plane * HW * HW;

    __shared__ float  red[16];
    __shared__ double sd[512];
    __shared__ int    amLast;

    // one-time zero of column borders (emits only touch [5,516])
#pragma unroll
    for (int b = 0; b < 2; ++b)
#pragma unroll
        for (int p = 0; p < 4; ++p)
#pragma unroll
            for (int s = 0; s < 4; ++s) {
                float* bb = (float*)(dynbuf + ((b*4 + p)*4 + s) * VB4);
                if (c < 5)    bb[c] = 0.f;
                if (c >= 501) bb[c + 16] = 0.f;   // 517..527
            }

    __syncthreads();

    const int rr = c >> 7;            // horizontal: row within group
    const int cq = c & 127;           // horizontal: float4 index

    float lsum;
    if (band == 0 || band == NBANDS - 1)
        lsum = band_body<true >(p1, p2, o0, dynbuf, c, rr, cq);
    else
        lsum = band_body<false>(p1, p2, o0, dynbuf, c, rr, cq);

    // ── block reduction ──
    float v = lsum;
#pragma unroll
    for (int off = 16; off; off >>= 1)
        v += __shfl_xor_sync(0xFFFFFFFFu, v, off);
    if ((c & 31) == 0) red[c >> 5] = v;
    __syncthreads();

    if (c == 0) {
        float bs = 0.f;
#pragma unroll
        for (int w = 0; w < 16; ++w) bs += red[w];
        g_part[plane * NBANDS + band] = bs;
        __threadfence();
        const unsigned t = atomicAdd(&g_count, 1u);
        amLast = (t == NBLK - 1);
    }
    __syncthreads();

    if (amLast) {
        __threadfence();
        double s = 0.0;
        for (int i = c; i < NBLK; i += 512) s += (double)g_part[i];
        sd[c] = s;
        __syncthreads();
#pragma unroll
        for (int k = 256; k > 0; k >>= 1) {
            if (c < k) sd[c] += sd[c + k];
            __syncthreads();
        }
        if (c == 0) {
            out[0]  = (float)(1.0 - sd[0] / 25165824.0);  // 32*3*512*512
            g_count = 0;                                   // reset for replay
        }
    }
}

extern "C" void kernel_launch(void* const* d_in, const int* in_sizes, int n_in,
                              void* d_out, int out_size)
{
    (void)in_sizes; (void)n_in; (void)out_size;
    const float* img1 = (const float*)d_in[0];
    const float* img2 = (const float*)d_in[1];
    cudaFuncSetAttribute(ssim_main, cudaFuncAttributeMaxDynamicSharedMemorySize,
                         SMEM_DYN);
    dim3 grid(NBANDS, NPLANES);
    ssim_main<<<grid, 512, SMEM_DYN>>>(img1, img2, (float*)d_out);
}

// round 11
// speedup vs baseline: 1.1404x; 1.0976x over previous
#include <cuda_runtime.h>

// SSIM loss, fully fused one-kernel version, 4-plane formulation.
// img1, img2: [32,3,512,512] fp32. Output: scalar fp32 = 1 - mean(ssim_map).
//
// Planes: conv(x), conv(y), conv(x^2+y^2), conv(x*y) (x²,y² folded pre-conv).
// Per block: one (plane, 44-row band), 512 threads. Vertical 11-tap conv via
// 11-phase register accumulator ring (1 col/thread); rows staged in 8-row
// double-buffered groups (5x8 + 1x4 tail), ONE barrier per 8 rows; horizontal
// 11-tap conv + SSIM at 4 px/thread (LDS.128, conflict-free 16B stride).
// Exactly R7's instruction inventory; only the barrier structure changed.

#define HW       512
#define NPLANES  96
#define BAND     44
#define NBANDS   12
#define NBLK     (NBANDS * NPLANES)   // 1152
#define VB       528
#define VB4      (VB / 4)             // 132
#define SMEM_DYN (2 * 4 * 8 * VB4 * 16)   // 135168 bytes

namespace {
constexpr double G_[6] = {0.0038659201595884, 0.0285655007845504,
                          0.1353352832366127, 0.4111122905071874,
                          0.8007374029168081, 1.0};
constexpr double GSUM = 2.0*(G_[0]+G_[1]+G_[2]+G_[3]+G_[4]) + 1.0;
constexpr float gwf(int j){ return (float)(G_[j < 6 ? j : 10 - j] / GSUM); }
}

__device__ constexpr float GW[11] = {
    gwf(0), gwf(1), gwf(2), gwf(3), gwf(4), gwf(5),
    gwf(6), gwf(7), gwf(8), gwf(9), gwf(10)};

__device__ float    g_part[NBLK];
__device__ unsigned g_count = 0;

// Deposit j of ingested row (ring phase PH) -> slot (PH+j+6)%11, belonging to
// output row o = r + j - 5. JMIN masks prologue deposits (only o >= o0).
// j == 10 is always the FIRST write to its slot since that slot's emit
// (validated R6/R7: identical rel_err) -> plain MUL, no ring init anywhere.
// Planes: 0 = x, 1 = y, 2 = x^2 + y^2, 3 = x*y.
template<int PH, int JMIN>
__device__ __forceinline__ void ingest(float (&A)[4][11], float v1, float v2)
{
    const float q2  = v1 * v1;
    const float q23 = fmaf(v2, v2, q2);
    const float q4  = v1 * v2;
#pragma unroll
    for (int j = JMIN; j < 11; ++j) {
        const int   s = (PH + j + 6) % 11;
        const float w = GW[j];
        if (j == 10) {
            A[0][s] = w * v1;
            A[1][s] = w * v2;
            A[2][s] = w * q23;
            A[3][s] = w * q4;
        } else {
            A[0][s] = fmaf(w, v1,  A[0][s]);
            A[1][s] = fmaf(w, v2,  A[1][s]);
            A[2][s] = fmaf(w, q23, A[2][s]);
            A[3][s] = fmaf(w, q4,  A[3][s]);
        }
    }
}

__global__ __launch_bounds__(512, 1)
void ssim_main(const float* __restrict__ img1, const float* __restrict__ img2,
               float* __restrict__ out)
{
    extern __shared__ float4 dynbuf[];   // [2][4][8][VB4]
#define VBUF(B, P, S) ((float*)(dynbuf + (((B)*4 + (P))*8 + (S)) * VB4))

    const int c     = threadIdx.x;
    const int band  = blockIdx.x;
    const int plane = blockIdx.y;
    const int o0    = band * BAND;
    const float* __restrict__ p1 = img1 + (size_t)plane * HW * HW;
    const float* __restrict__ p2 = img2 + (size_t)plane * HW * HW;

    __shared__ float  red[16];
    __shared__ double sd[512];
    __shared__ int    amLast;

    // one-time zero of column borders (emits only touch [5,516])
#pragma unroll
    for (int b = 0; b < 2; ++b)
#pragma unroll
        for (int p = 0; p < 4; ++p)
#pragma unroll
            for (int s = 0; s < 8; ++s) {
                float* bb = VBUF(b, p, s);
                if (c < 5)    bb[c] = 0.f;
                if (c >= 501) bb[c + 16] = 0.f;   // 517..527
            }

    float acc[4][11];   // no init: first touch of every slot is the j==10 MUL

    __syncthreads();

    // two 4-row prefetch banks (A: sub-rows 0-3, B: sub-rows 4-7 of a group)
    float nA1[4], nA2[4], nB1[4], nB2[4];
    // load ingest rows r0..r0+3 into bank A / B (guarded; r may exceed 511)
#define LOADS_A(r0) {                                                        \
        _Pragma("unroll")                                                    \
        for (int i = 0; i < 4; ++i) {                                        \
            const int  r_  = (r0) + i;                                       \
            const bool ok_ = r_ < HW;                                        \
            nA1[i] = ok_ ? __ldg(&p1[(size_t)r_ * HW + c]) : 0.f;            \
            nA2[i] = ok_ ? __ldg(&p2[(size_t)r_ * HW + c]) : 0.f;            \
        } }
#define LOADS_B(r0) {                                                        \
        _Pragma("unroll")                                                    \
        for (int i = 0; i < 4; ++i) {                                        \
            const int  r_  = (r0) + i;                                       \
            const bool ok_ = r_ < HW;                                        \
            nB1[i] = ok_ ? __ldg(&p1[(size_t)r_ * HW + c]) : 0.f;            \
            nB2[i] = ok_ ? __ldg(&p2[(size_t)r_ * HW + c]) : 0.f;            \
        } }

    // issue group-0 ingest loads first; prologue FMA chain hides the latency
    LOADS_A(o0 + 5)
    LOADS_B(o0 + 9)

    // ── prologue: rows o0-5 .. o0+4, JMIN = 10-i masking ──
#define PROLOG(i) {                                                          \
        const int  r_  = o0 - 5 + (i);                                       \
        const bool ok_ = (unsigned)r_ < (unsigned)HW;                        \
        const float v1_ = ok_ ? __ldg(&p1[(size_t)r_ * HW + c]) : 0.f;       \
        const float v2_ = ok_ ? __ldg(&p2[(size_t)r_ * HW + c]) : 0.f;       \
        ingest<((i) + 6) % 11, 10 - (i)>(acc, v1_, v2_); }
    PROLOG(0) PROLOG(1) PROLOG(2) PROLOG(3) PROLOG(4)
    PROLOG(5) PROLOG(6) PROLOG(7) PROLOG(8) PROLOG(9)
#undef PROLOG

    // ingest + emit step T (= band-local output row): row o0+T+5, ring phase
    // (T+5)%11, emit slot T%11, buffer BUF, staging sub-row T%8 (or i for F).
#define ING(T, BUF, SR, V1, V2) {                                            \
        ingest<((T) + 5) % 11, 0>(acc, V1, V2);                              \
        _Pragma("unroll")                                                    \
        for (int p = 0; p < 4; ++p)                                          \
            VBUF(BUF, p, (SR))[c + 5] = acc[p][(T) % 11]; }

    // 8 ingest steps of double-group G (T = 8G..8G+7), buffer G&1
#define ING8(G)                                                              \
        ING(8*(G)+0, (G)&1, 0, nA1[0], nA2[0])                               \
        ING(8*(G)+1, (G)&1, 1, nA1[1], nA2[1])                               \
        ING(8*(G)+2, (G)&1, 2, nA1[2], nA2[2])                               \
        ING(8*(G)+3, (G)&1, 3, nA1[3], nA2[3])                               \
        ING(8*(G)+4, (G)&1, 4, nB1[0], nB2[0])                               \
        ING(8*(G)+5, (G)&1, 5, nB1[1], nB2[1])                               \
        ING(8*(G)+6, (G)&1, 6, nB1[2], nB2[2])                               \
        ING(8*(G)+7, (G)&1, 7, nB1[3], nB2[3])

    float lsum = 0.f;
    const int rr = c >> 7;            // horizontal: row within 4-row half
    const int cq = c & 127;           // horizontal: float4 index

    // horizontal conv + SSIM for 4 output rows starting at band-local row
    // TB (= staging sub-rows SR0+rr) out of buffer B (R7's exact 4px shape)
#define HSTEP(TB, B, SR0) {                                                  \
        float hr[4][4];                                                      \
        _Pragma("unroll")                                                    \
        for (int p = 0; p < 4; ++p) {                                        \
            const float4* q = dynbuf + (((B)*4 + p)*8 + (SR0) + rr) * VB4 + cq; \
            const float4 A = q[0], Bv = q[1], Cv = q[2], D = q[3];           \
            const float v[16] = {A.x, A.y, A.z, A.w,  Bv.x, Bv.y, Bv.z, Bv.w,\
                                 Cv.x, Cv.y, Cv.z, Cv.w,  D.x, D.y, D.z, D.w};\
            _Pragma("unroll")                                                \
            for (int i = 0; i < 4; ++i) {                                    \
                float s = GW[0] * v[i];                                      \
                _Pragma("unroll")                                            \
                for (int k = 1; k < 11; ++k) s = fmaf(GW[k], v[i + k], s);   \
                hr[p][i] = s;                                                \
            }                                                                \
        }                                                                    \
        if ((o0 + (TB) + rr) < HW) {                                         \
            _Pragma("unroll")                                                \
            for (int i = 0; i < 4; ++i) {                                    \
                const float C1 = 1e-4f, C2 = 9e-4f;                          \
                const float m1 = hr[0][i], m2 = hr[1][i];                    \
                const float mu12 = m1 * m2;                                  \
                const float msum = fmaf(m1, m1, m2 * m2);                    \
                const float Anum = 2.f * mu12 + C1;                          \
                const float Bnum = 2.f * (hr[3][i] - mu12) + C2;             \
                const float Cden = msum + C1;                                \
                const float Dden = (hr[2][i] - msum) + C2;                   \
                lsum += __fdividef(Anum * Bnum, Cden * Dden);                \
            }                                                                \
        } }

    // double-group 0: ingest banks already loaded, emit buf 0
    ING8(0)

    // double-groups 1..4: one barrier per 8 rows; 2 HSTEPs of G-1; ING8(G)
#define GBODY(G) {                                                           \
        __syncthreads();                                                     \
        LOADS_A(o0 + 8 * (G) + 5)                                            \
        HSTEP(8 * ((G) - 1),     ((G) - 1) & 1, 0)                           \
        LOADS_B(o0 + 8 * (G) + 9)                                            \
        HSTEP(8 * ((G) - 1) + 4, ((G) - 1) & 1, 4)                           \
        ING8(G) }
    GBODY(1) GBODY(2) GBODY(3) GBODY(4)
#undef GBODY

    // tail: 4-row group F (T = 40..43) into buf 1; HSTEPs of group 4 (buf 0)
    __syncthreads();
    LOADS_A(o0 + 45)
    HSTEP(32, 0, 0)
    HSTEP(36, 0, 4)
    ING(40, 1, 0, nA1[0], nA2[0])
    ING(41, 1, 1, nA1[1], nA2[1])
    ING(42, 1, 2, nA1[2], nA2[2])
    ING(43, 1, 3, nA1[3], nA2[3])

    __syncthreads();
    HSTEP(40, 1, 0)

#undef HSTEP
#undef ING8
#undef ING
#undef LOADS_A
#undef LOADS_B
#undef VBUF

    // ── block reduction ──
    float v = lsum;
#pragma unroll
    for (int off = 16; off; off >>= 1)
        v += __shfl_xor_sync(0xFFFFFFFFu, v, off);
    if ((c & 31) == 0) red[c >> 5] = v;
    __syncthreads();

    if (c == 0) {
        float bs = 0.f;
#pragma unroll
        for (int w = 0; w < 16; ++w) bs += red[w];
        g_part[plane * NBANDS + band] = bs;
        __threadfence();
        const unsigned t = atomicAdd(&g_count, 1u);
        amLast = (t == NBLK - 1);
    }
    __syncthreads();

    if (amLast) {
        __threadfence();
        double s = 0.0;
        for (int i = c; i < NBLK; i += 512) s += (double)g_part[i];
        sd[c] = s;
        __syncthreads();
#pragma unroll
        for (int k = 256; k > 0; k >>= 1) {
            if (c < k) sd[c] += sd[c + k];
            __syncthreads();
        }
        if (c == 0) {
            out[0]  = (float)(1.0 - sd[0] / 25165824.0);  // 32*3*512*512
            g_count = 0;                                   // reset for replay
        }
    }
}

extern "C" void kernel_launch(void* const* d_in, const int* in_sizes, int n_in,
                              void* d_out, int out_size)
{
    (void)in_sizes; (void)n_in; (void)out_size;
    const float* img1 = (const float*)d_in[0];
    const float* img2 = (const float*)d_in[1];
    cudaFuncSetAttribute(ssim_main, cudaFuncAttributeMaxDynamicSharedMemorySize,
                         SMEM_DYN);
    dim3 grid(NBANDS, NPLANES);
    ssim_main<<<grid, 512, SMEM_DYN>>>(img1, img2, (float*)d_out);
}